// round 7
// baseline (speedup 1.0000x reference)
#include <cuda_runtime.h>
#include <cuda_bf16.h>
#include <cstdint>
#include <cstddef>

// ---------------------------------------------------------------------------
// CVAE forward, Round 5: dataflow flags replace per-step barriers.
// bf16 mma, gate-grouped accumulators, per-utile epoch flags + quarter-wise
// cp.async, prefetched additive terms, MUFU epilogue.
// B=256 T=128 U=512 LAT=200 V=42 P=3
// ---------------------------------------------------------------------------

constexpr int cB = 256, cT = 128, cU = 512, cLAT = 200, cV = 42, cP = 3;
constexpr int G4U = 2048;
constexpr int NTHR = 256, NCTA = 128;

// ------------------------------- scratch -----------------------------------
__device__ float g_pre[(size_t)cB * cT * G4U];           // 256 MB
__device__ __nv_bfloat16 g_seq[(size_t)cB * cT * cU];    // dec layer2 out
__device__ __nv_bfloat16 g_himg[4][2][32768];            // per-bgroup h image
__device__ float g_c[cB * cU];
__device__ float g_Eenc[cV * G4U];
__device__ float g_Edec[cV * G4U];
__device__ float g_CbEnc[cB * G4U];
__device__ float g_CbDec[cB * G4U];
__device__ float g_Cz[cB * G4U];
__device__ float g_z[cB * cLAT];
__device__ float g_latpart[cB];
__device__ float g_reconpart[512];
__device__ unsigned g_bar2[24];
__device__ unsigned g_flag[6 * 4 * 32];                  // per pass/bgroup/utile

// ------------------------------ helpers ------------------------------------
__device__ __forceinline__ void cpa16(void* d, const void* s) {
    unsigned ds = (unsigned)__cvta_generic_to_shared(d);
    asm volatile("cp.async.cg.shared.global [%0], [%1], 16;" :: "r"(ds), "l"(s));
}

__device__ __forceinline__ void mma16(float* c, uint4 a, uint2 b) {
    asm volatile(
        "mma.sync.aligned.m16n8k16.row.col.f32.bf16.bf16.f32 "
        "{%0,%1,%2,%3},{%4,%5,%6,%7},{%8,%9},{%0,%1,%2,%3};"
        : "+f"(c[0]), "+f"(c[1]), "+f"(c[2]), "+f"(c[3])
        : "r"(a.x), "r"(a.y), "r"(a.z), "r"(a.w), "r"(b.x), "r"(b.y));
}

__device__ __forceinline__ float sigf(float x) {
    float r;
    asm("{\n\t.reg .f32 t;\n\t"
        "mul.f32 t, %1, 0fBFB8AA3B;\n\t"
        "ex2.approx.f32 t, t;\n\t"
        "add.f32 t, t, 0f3F800000;\n\t"
        "rcp.approx.f32 %0, t;\n\t}"
        : "=f"(r) : "f"(x));
    return r;
}

__device__ __forceinline__ float tanha(float x) {
    float r;
    asm("tanh.approx.f32 %0, %1;" : "=f"(r) : "f"(x));
    return r;
}

// initial-sync barrier (per pass/bgroup, used once)
__device__ __forceinline__ void barrel(unsigned* ctr, unsigned target) {
    __syncthreads();
    if (threadIdx.x == 0) {
        asm volatile("red.release.gpu.global.add.u32 [%0], 1;" :: "l"(ctr) : "memory");
        unsigned v;
        do {
            asm volatile("ld.acquire.gpu.global.u32 %0, [%1];" : "=r"(v) : "l"(ctr) : "memory");
        } while (v < target);
    }
    __syncthreads();
}

// wait until 8 producer flags (f[0..7]) reach tgt; warp-converged.
__device__ __forceinline__ void waitq(const unsigned* f, unsigned tgt, int lane) {
    unsigned done;
    do {
        unsigned v = tgt;
        if (lane < 8)
            asm volatile("ld.acquire.gpu.global.u32 %0, [%1];"
                         : "=r"(v) : "l"(f + lane) : "memory");
        done = __ballot_sync(0xffffffffu, v >= tgt);
    } while (done != 0xffffffffu);
}

// ------------------------------ prep kernel --------------------------------
__global__ void prep_kernel(const float* __restrict__ emb_enc,
                            const float* __restrict__ emb_dec,
                            const float* __restrict__ enc_k0,
                            const float* __restrict__ dec_k0,
                            const float* __restrict__ enc_b0,
                            const float* __restrict__ dec_b0,
                            const float* __restrict__ Cmat) {
    const int bid = blockIdx.x, tid = threadIdx.x;
    if (bid < 42) {
        const int v = bid;
        for (int n = tid; n < G4U; n += NTHR) {
            float acc = 0.f;
            for (int l = 0; l < cLAT; l++)
                acc += emb_enc[v * cLAT + l] * enc_k0[l * G4U + n];
            g_Eenc[v * G4U + n] = acc;
        }
    } else if (bid < 84) {
        const int v = bid - 42;
        for (int n = tid; n < G4U; n += NTHR) {
            float acc = 0.f;
            for (int l = 0; l < cLAT; l++)
                acc += emb_dec[v * cLAT + l] * dec_k0[(cLAT + l) * G4U + n];
            g_Edec[v * G4U + n] = acc;
        }
    } else if (bid < 340) {
        const int b = bid - 84;
        for (int n = tid; n < G4U; n += NTHR) {
            float acc = enc_b0[n];
            for (int p = 0; p < cP; p++)
                acc += Cmat[b * cP + p] * enc_k0[(cLAT + p) * G4U + n];
            g_CbEnc[b * G4U + n] = acc;
        }
    } else if (bid < 596) {
        const int b = bid - 340;
        for (int n = tid; n < G4U; n += NTHR) {
            float acc = dec_b0[n];
            for (int p = 0; p < cP; p++)
                acc += Cmat[b * cP + p] * dec_k0[(2 * cLAT + p) * G4U + n];
            g_CbDec[b * G4U + n] = acc;
        }
    } else {
        for (int i = tid; i < 6 * 4 * 32; i += NTHR) g_flag[i] = 0u;
        if (tid < 24) g_bar2[tid] = 0u;
    }
}

// --------------------------- recurrent kernel ------------------------------
// 128 CTAs = 4 bgroups(64 rows) x 32 utiles(16 units -> 64 gate cols).
template <bool L0, bool FUSE, bool WRSEQ>
__global__ __launch_bounds__(256, 1)
void rec5_kernel(const float* __restrict__ Wr, const float* __restrict__ Wk,
                 const float* __restrict__ bnext, const int* __restrict__ Xidx,
                 int sel_dec, int pass_id) {
    extern __shared__ unsigned sm[];
    unsigned* WrS = sm;                                   // 64KB
    unsigned* WkS = sm + 16384;                           // 64KB if FUSE
    constexpr int AOFF = FUSE ? 32768 : 16384;
    unsigned* Asm = sm + AOFF;                            // 64KB
    __nv_bfloat16* hbuf = (__nv_bfloat16*)(sm + AOFF + 16384);  // 2KB

    const int tid = threadIdx.x, lane = tid & 31, w = tid >> 5;
    const int wm = w & 3, wn = w >> 2;
    const int bg = blockIdx.x >> 5;
    const int b0 = bg * 64;
    const int utile = blockIdx.x & 31;
    const int u0 = utile * 16;

    // ---- permute weights into smem (bf16 fragment layout, gate-grouped) ----
    for (int i = tid; i < 16384; i += 256) {
        int c = i & 63, kp = i >> 6, k = kp * 2;
        int grp = c >> 3, j = c & 7;
        int gcol = (grp & 3) * 512 + u0 + (grp >> 2) * 8 + j;
        int chunk = k >> 4, kk = k & 15;
        int ln = j * 4 + ((kk & 7) >> 1);
        int reg = kk >> 3;
        int off = ((grp * 32 + chunk) * 32 + ln) * 2 + reg;
        {
            __nv_bfloat162 p = __floats2bfloat162_rn(
                Wr[(size_t)k * G4U + gcol], Wr[(size_t)(k + 1) * G4U + gcol]);
            WrS[off] = *(unsigned*)&p;
        }
        if (FUSE) {
            __nv_bfloat162 p = __floats2bfloat162_rn(
                Wk[(size_t)k * G4U + gcol], Wk[(size_t)(k + 1) * G4U + gcol]);
            WkS[off] = *(unsigned*)&p;
        }
    }
    // ---- zero my 1/32 of both h-image buffers ----
    {
        uint4* p0 = (uint4*)&g_himg[bg][0][0];
        uint4* p1 = (uint4*)&g_himg[bg][1][0];
        int base = utile * 128;
        if (tid < 128) {
            p0[base + tid] = make_uint4(0, 0, 0, 0);
            p1[base + tid] = make_uint4(0, 0, 0, 0);
        }
    }
    barrel(&g_bar2[pass_id * 4 + bg], 32);   // zero-images visible

    const float* Etab = sel_dec ? g_Edec : g_Eenc;
    const float* Cb = sel_dec ? g_Cz : g_CbEnc;
    const unsigned* flg = &g_flag[(pass_id * 4 + bg) * 32];
    unsigned* myflag = &g_flag[(pass_id * 4 + bg) * 32 + utile];

    const int r0 = wm * 16 + (lane >> 2);       // local row base (0..63)
    const int ul0 = wn * 8 + (lane & 3) * 2;    // unit base within 16

    // ---- preload static per-thread adds ----
    float2 cbv[2][4];
    if (L0) {
#pragma unroll
        for (int rr = 0; rr < 2; rr++)
#pragma unroll
            for (int g = 0; g < 4; g++)
                cbv[rr][g] = *(const float2*)&Cb[(size_t)(b0 + r0 + rr * 8) * G4U +
                                                 g * 512 + u0 + ul0];
    }
    float2 bb[4];
    if (FUSE) {
#pragma unroll
        for (int g = 0; g < 4; g++)
            bb[g] = *(const float2*)&bnext[g * 512 + u0 + ul0];
    }

    float cst[4] = {0.f, 0.f, 0.f, 0.f};

    constexpr int TMAX = FUSE ? 129 : 128;
    for (int t = 0; t < TMAX; t++) {
        const bool doR = (t < 128);
        const bool doK = FUSE && (t > 0);
        const __nv_bfloat16* img = &g_himg[bg][t & 1][0];

        // poll producers per quarter, then issue that quarter's cp.async
#pragma unroll
        for (int q = 0; q < 4; q++) {
            if (t > 0) waitq(flg + q * 8, (unsigned)t, lane);
#pragma unroll
            for (int j = 0; j < 4; j++) {
                int idx = tid + j * 256;           // 0..1023
                int strip = idx >> 8, wi = idx & 255;
                int chunk = q * 8 + (wi >> 5), ln = wi & 31;
                int off16 = (strip * 32 + chunk) * 32 + ln;
                cpa16((char*)Asm + (size_t)off16 * 16,
                      (const char*)img + (size_t)off16 * 16);
            }
            asm volatile("cp.async.commit_group;");
        }

        // ---- prefetch additive terms (off critical path) ----
        float2 zadd[2][4];
        if (doR) {
            if (L0) {
                int xi0 = Xidx[(b0 + r0) * cT + t];
                int xi1 = Xidx[(b0 + r0 + 8) * cT + t];
#pragma unroll
                for (int g = 0; g < 4; g++) {
                    float2 e0 = *(const float2*)&Etab[xi0 * G4U + g * 512 + u0 + ul0];
                    float2 e1 = *(const float2*)&Etab[xi1 * G4U + g * 512 + u0 + ul0];
                    zadd[0][g] = make_float2(e0.x + cbv[0][g].x, e0.y + cbv[0][g].y);
                    zadd[1][g] = make_float2(e1.x + cbv[1][g].x, e1.y + cbv[1][g].y);
                }
            } else {
#pragma unroll
                for (int rr = 0; rr < 2; rr++)
#pragma unroll
                    for (int g = 0; g < 4; g++)
                        zadd[rr][g] = __ldcs((const float2*)&g_pre[
                            ((size_t)(b0 + r0 + rr * 8) * cT + t) * G4U +
                            g * 512 + u0 + ul0]);
            }
        }

        float accR[4][4], accK[4][4];
#pragma unroll
        for (int g = 0; g < 4; g++)
#pragma unroll
            for (int q = 0; q < 4; q++) { accR[g][q] = 0.f; accK[g][q] = 0.f; }

#pragma unroll
        for (int q = 0; q < 4; q++) {
            if (q == 0) asm volatile("cp.async.wait_group 3;" ::: "memory");
            else if (q == 1) asm volatile("cp.async.wait_group 2;" ::: "memory");
            else if (q == 2) asm volatile("cp.async.wait_group 1;" ::: "memory");
            else asm volatile("cp.async.wait_group 0;" ::: "memory");
            __syncthreads();
#pragma unroll
            for (int ch = 0; ch < 8; ch++) {
                int chunk = q * 8 + ch;
                uint4 af = *(const uint4*)(Asm + ((wm * 32 + chunk) * 32 + lane) * 4);
                if (doR) {
#pragma unroll
                    for (int g = 0; g < 4; g++) {
                        uint2 bf = *(const uint2*)(WrS + (((wn * 4 + g) * 32 + chunk) * 32 + lane) * 2);
                        mma16(accR[g], af, bf);
                    }
                }
                if (doK) {
#pragma unroll
                    for (int g = 0; g < 4; g++) {
                        uint2 bf = *(const uint2*)(WkS + (((wn * 4 + g) * 32 + chunk) * 32 + lane) * 2);
                        mma16(accK[g], af, bf);
                    }
                }
            }
        }

        // ---- fused pre write (projection of h_{t-1} for next layer) ----
        if (doK) {
#pragma unroll
            for (int g = 0; g < 4; g++) {
                size_t o1 = ((size_t)(b0 + r0) * cT + (t - 1)) * G4U + g * 512 + u0 + ul0;
                size_t o2 = ((size_t)(b0 + r0 + 8) * cT + (t - 1)) * G4U + g * 512 + u0 + ul0;
                __stcs((float2*)&g_pre[o1],
                       make_float2(accK[g][0] + bb[g].x, accK[g][1] + bb[g].y));
                __stcs((float2*)&g_pre[o2],
                       make_float2(accK[g][2] + bb[g].x, accK[g][3] + bb[g].y));
            }
        }

        // ---- recurrence epilogue (gates in-register, MUFU math) ----
        if (doR) {
#pragma unroll
            for (int rr = 0; rr < 2; rr++) {
                const int row = r0 + rr * 8;
                const int b = b0 + row;
#pragma unroll
                for (int pq = 0; pq < 2; pq++) {
                    const int q = rr * 2 + pq;
                    float zi = accR[0][q] + (pq ? zadd[rr][0].y : zadd[rr][0].x);
                    float zf = accR[1][q] + (pq ? zadd[rr][1].y : zadd[rr][1].x);
                    float zg = accR[2][q] + (pq ? zadd[rr][2].y : zadd[rr][2].x);
                    float zo = accR[3][q] + (pq ? zadd[rr][3].y : zadd[rr][3].x);
                    float ig = sigf(zi);
                    float fg = sigf(zf);
                    float gv = tanhf(zg);
                    float og = sigf(zo);
                    cst[q] = fg * cst[q] + ig * gv;
                    float h2 = og * tanha(cst[q]);
                    const int ul = ul0 + pq;
                    const int strip = row >> 4, rr2 = row & 15;
                    const int ln2 = (rr2 & 7) * 4 + ((ul & 7) >> 1);
                    const int reg = (rr2 >> 3) + 2 * (ul >> 3);
                    hbuf[strip * 256 + ln2 * 8 + reg * 2 + (ul & 1)] = __float2bfloat16(h2);
                    if (WRSEQ)
                        g_seq[((size_t)b * cT + t) * cU + u0 + ul] = __float2bfloat16(h2);
                }
            }
            __syncthreads();
            // coalesced publish: 128 x uint4
            if (tid < 128) {
                __nv_bfloat16* imgout = &g_himg[bg][(t + 1) & 1][0];
                int strip = tid >> 5, ln = tid & 31;
                uint4 v = ((const uint4*)hbuf)[strip * 32 + ln];
                ((uint4*)imgout)[(strip * 32 + utile) * 32 + ln] = v;
            }
            __syncthreads();
            if (tid == 0)
                asm volatile("red.release.gpu.global.add.u32 [%0], 1;"
                             :: "l"(myflag) : "memory");
        }
    }

    // ---- final cell state ----
#pragma unroll
    for (int rr = 0; rr < 2; rr++)
#pragma unroll
        for (int pq = 0; pq < 2; pq++)
            g_c[(size_t)(b0 + r0 + rr * 8) * cU + u0 + ul0 + pq] = cst[rr * 2 + pq];
}

// ----------------------- latent: mean / log_sigma / z ----------------------
__global__ void latz_kernel(const float* __restrict__ Wm, const float* __restrict__ bm,
                            const float* __restrict__ Ws, const float* __restrict__ bs,
                            const float* __restrict__ eps) {
    __shared__ float csh[cU];
    __shared__ float red[NTHR];
    const int b = blockIdx.x, tid = threadIdx.x;
    csh[tid] = g_c[b * cU + tid];
    csh[tid + 256] = g_c[b * cU + tid + 256];
    __syncthreads();
    float term = 0.f;
    if (tid < cLAT) {
        float m = bm[tid], ls = bs[tid];
        for (int u = 0; u < cU; u++) {
            const float cv = csh[u];
            m += cv * Wm[u * cLAT + tid];
            ls += cv * Ws[u * cLAT + tid];
        }
        g_z[b * cLAT + tid] = m + expf(0.5f * ls) * eps[b * cLAT + tid];
        term = 1.f + ls - m * m - expf(ls);
    }
    red[tid] = term;
    __syncthreads();
    for (int s = 128; s > 0; s >>= 1) {
        if (tid < s) red[tid] += red[tid + s];
        __syncthreads();
    }
    if (tid == 0) g_latpart[b] = red[0];
}

// ------------------------------- z projection ------------------------------
__global__ void zproj_kernel(const float* __restrict__ dec_k0) {
    __shared__ float zsh[cLAT];
    const int b = blockIdx.x, tid = threadIdx.x;
    if (tid < cLAT) zsh[tid] = g_z[b * cLAT + tid];
    __syncthreads();
    for (int n = tid; n < G4U; n += NTHR) {
        float acc = g_CbDec[b * G4U + n];
        for (int l = 0; l < cLAT; l++) acc += zsh[l] * dec_k0[l * G4U + n];
        g_Cz[b * G4U + n] = acc;
    }
}

// ----------------------- output logits + masked CE -------------------------
__global__ void ce_kernel(const float* __restrict__ Wo, const float* __restrict__ bo,
                          const int* __restrict__ Y, const int* __restrict__ Lv) {
    __shared__ float hsh[8][cU];
    __shared__ float wred[8];
    const int tid = threadIdx.x, w = tid >> 5, lane = tid & 31;
    const int gw = blockIdx.x * 8 + w;
    float sum = 0.f;
    for (int j = 0; j < 8; j++) {
        const int idx = gw + j * 4096;
        const int b = idx >> 7, t = idx & 127;
        const __nv_bfloat16* hp = &g_seq[((size_t)b * cT + t) * cU];
        for (int i = lane; i < cU; i += 32) hsh[w][i] = __bfloat162float(hp[i]);
        __syncwarp();
        const int v0 = lane;
        const int v1 = 32 + lane;
        const int v1c = (v1 < cV) ? v1 : 0;
        float l0 = bo[v0];
        float l1 = bo[v1c];
        for (int u = 0; u < cU; u++) {
            const float hv = hsh[w][u];
            l0 += hv * Wo[u * cV + v0];
            l1 += hv * Wo[u * cV + v1c];
        }
        if (v1 >= cV) l1 = -1e30f;
        float mx = fmaxf(l0, l1);
        for (int o = 16; o; o >>= 1) mx = fmaxf(mx, __shfl_xor_sync(~0u, mx, o));
        float s = expf(l0 - mx) + ((v1 < cV) ? expf(l1 - mx) : 0.f);
        for (int o = 16; o; o >>= 1) s += __shfl_xor_sync(~0u, s, o);
        const float lse = mx + logf(s);
        const int y = Y[b * cT + t];
        const float ly = __shfl_sync(~0u, (y < 32) ? l0 : l1, y & 31);
        if (lane == 0 && t < Lv[b]) sum += (lse - ly);
        __syncwarp();
    }
    if (lane == 0) wred[w] = sum;
    __syncthreads();
    if (tid == 0) {
        float s = 0.f;
        for (int i = 0; i < 8; i++) s += wred[i];
        g_reconpart[blockIdx.x] = s;
    }
}

// ------------------------------- final reduce ------------------------------
__global__ void finish_kernel(float* __restrict__ out, int out_size) {
    __shared__ float red[NTHR];
    const int tid = threadIdx.x;
    float s = 0.f;
    for (int i = tid; i < 512; i += NTHR) s += g_reconpart[i];
    red[tid] = s;
    __syncthreads();
    for (int st = 128; st > 0; st >>= 1) {
        if (tid < st) red[tid] += red[tid + st];
        __syncthreads();
    }
    const float rsum = red[0];
    __syncthreads();
    float s2 = 0.f;
    for (int i = tid; i < cB; i += NTHR) s2 += g_latpart[i];
    red[tid] = s2;
    __syncthreads();
    for (int st = 128; st > 0; st >>= 1) {
        if (tid < st) red[tid] += red[tid + st];
        __syncthreads();
    }
    if (tid == 0) {
        const float recon = rsum / (float)(cB * cT);
        const float lat = -0.5f * red[0] / (float)(cB * cLAT);
        out[0] = recon + lat;
        if (out_size > 1) out[1] = recon;
        if (out_size > 2) out[2] = lat;
    }
}

// --------------------------------- launch ----------------------------------
extern "C" void kernel_launch(void* const* d_in, const int* in_sizes, int n_in,
                              void* d_out, int out_size) {
    const int* X = (const int*)d_in[0];
    const int* Y = (const int*)d_in[1];
    const float* C = (const float*)d_in[2];
    const int* L = (const int*)d_in[3];
    const float* eps = (const float*)d_in[4];
    const float* emb_enc = (const float*)d_in[5];
    const float* emb_dec = (const float*)d_in[6];
    const float* enc_k0 = (const float*)d_in[7];
    const float* enc_rk0 = (const float*)d_in[8];
    const float* enc_b0 = (const float*)d_in[9];
    const float* enc_k1 = (const float*)d_in[10];
    const float* enc_rk1 = (const float*)d_in[11];
    const float* enc_b1 = (const float*)d_in[12];
    const float* enc_k2 = (const float*)d_in[13];
    const float* enc_rk2 = (const float*)d_in[14];
    const float* enc_b2 = (const float*)d_in[15];
    const float* dec_k0 = (const float*)d_in[16];
    const float* dec_rk0 = (const float*)d_in[17];
    const float* dec_b0 = (const float*)d_in[18];
    const float* dec_k1 = (const float*)d_in[19];
    const float* dec_rk1 = (const float*)d_in[20];
    const float* dec_b1 = (const float*)d_in[21];
    const float* dec_k2 = (const float*)d_in[22];
    const float* dec_rk2 = (const float*)d_in[23];
    const float* dec_b2 = (const float*)d_in[24];
    const float* Wm = (const float*)d_in[25];
    const float* bm = (const float*)d_in[26];
    const float* Ws = (const float*)d_in[27];
    const float* bs = (const float*)d_in[28];
    const float* Wo = (const float*)d_in[29];
    const float* bo = (const float*)d_in[30];

    const int SMF = (16384 * 3 + 512) * 4;   // 198,656 B (fused)
    const int SMP = (16384 * 2 + 512) * 4;   // 133,120 B (plain)
    cudaFuncSetAttribute((const void*)rec5_kernel<true, true, false>,
                         cudaFuncAttributeMaxDynamicSharedMemorySize, SMF);
    cudaFuncSetAttribute((const void*)rec5_kernel<false, true, false>,
                         cudaFuncAttributeMaxDynamicSharedMemorySize, SMF);
    cudaFuncSetAttribute((const void*)rec5_kernel<false, false, false>,
                         cudaFuncAttributeMaxDynamicSharedMemorySize, SMP);
    cudaFuncSetAttribute((const void*)rec5_kernel<false, false, true>,
                         cudaFuncAttributeMaxDynamicSharedMemorySize, SMP);

    prep_kernel<<<597, NTHR>>>(emb_enc, emb_dec, enc_k0, dec_k0, enc_b0, dec_b0, C);

    // ---- encoder ----
    rec5_kernel<true, true, false><<<NCTA, NTHR, SMF>>>(enc_rk0, enc_k1, enc_b1, X, 0, 0);
    rec5_kernel<false, true, false><<<NCTA, NTHR, SMF>>>(enc_rk1, enc_k2, enc_b2, nullptr, 0, 1);
    rec5_kernel<false, false, false><<<NCTA, NTHR, SMP>>>(enc_rk2, nullptr, nullptr, nullptr, 0, 2);

    // ---- latent ----
    latz_kernel<<<cB, NTHR>>>(Wm, bm, Ws, bs, eps);
    zproj_kernel<<<cB, NTHR>>>(dec_k0);

    // ---- decoder ----
    rec5_kernel<true, true, false><<<NCTA, NTHR, SMF>>>(dec_rk0, dec_k1, dec_b1, X, 1, 3);
    rec5_kernel<false, true, false><<<NCTA, NTHR, SMF>>>(dec_rk1, dec_k2, dec_b2, nullptr, 1, 4);
    rec5_kernel<false, false, true><<<NCTA, NTHR, SMP>>>(dec_rk2, nullptr, nullptr, nullptr, 1, 5);

    // ---- losses ----
    ce_kernel<<<512, NTHR>>>(Wo, bo, Y, L);
    finish_kernel<<<1, NTHR>>>((float*)d_out, out_size);
}